// round 4
// baseline (speedup 1.0000x reference)
#include <cuda_runtime.h>
#include <cstdint>

// ---------------------------------------------------------------------------
// DCNv2: B=8, Cin=Cout=256, H=W=64, K=3, S=1, P=1, D=1
// Inputs (metadata order): x[8,256,64,64], weight[256,256,3,3], bias[256],
//                          offset_w[27,256,3,3], offset_b[27]
// Output: [8,256,64,64] fp32
// ---------------------------------------------------------------------------

#define BDIM   8
#define CIN    256
#define COUT   256
#define HH     64
#define WW     64
#define KKN    9          // K*K
#define NPIX   4096       // H*W
#define MTOT   32768      // B*H*W
#define KDIM   2304       // Cin*KK

typedef unsigned long long ULL;

// ------------------------- scratch (device globals) ------------------------
__device__ float g_py[BDIM * KKN * NPIX];
__device__ float g_px[BDIM * KKN * NPIX];
__device__ float g_pm[BDIM * KKN * NPIX];
__device__ float g_A[(size_t)KDIM * MTOT];   // A matrix, K-major: g_A[k][m]

// ------------------------- f32x2 helpers -----------------------------------
static __device__ __forceinline__ ULL pack2(float lo, float hi) {
    ULL r;
    asm("mov.b64 %0, {%1,%2};" : "=l"(r) : "f"(lo), "f"(hi));
    return r;
}
static __device__ __forceinline__ void unpack2(ULL v, float& lo, float& hi) {
    asm("mov.b64 {%0,%1}, %2;" : "=f"(lo), "=f"(hi) : "l"(v));
}
static __device__ __forceinline__ void ffma2(ULL& d, ULL a, ULL b) {
    asm("fma.rn.f32x2 %0, %1, %2, %3;" : "=l"(d) : "l"(a), "l"(b), "l"(d));
}

// ===========================================================================
// Kernel 1: offset conv (3x3, pad 1) -> py / px / mask
//   Direct conv, 1 pixel per thread, 28-wide (padded 27) accumulator,
//   weights staged in SMEM as ws[c][kk][28] for float4 inner loads.
// ===========================================================================
__global__ __launch_bounds__(256) void offset_conv_kernel(
    const float* __restrict__ x,
    const float* __restrict__ ow,
    const float* __restrict__ ob)
{
    const int tid = threadIdx.x;
    const int m   = blockIdx.x * 256 + tid;
    const int b   = m >> 12;
    const int p   = m & 4095;
    const int ho  = p >> 6;
    const int wo  = p & 63;

    __shared__ __align__(16) float ws[32 * 9 * 28];   // 32.25 KB

    float acc[28];
#pragma unroll
    for (int i = 0; i < 28; i++) acc[i] = 0.f;

    const bool r0ok = (ho > 0), r2ok = (ho < 63);
    const bool c0ok = (wo > 0), c2ok = (wo < 63);

    for (int c0 = 0; c0 < CIN; c0 += 32) {
        __syncthreads();
        // stage weights: gmem-linear walk (coalesced), scatter-store to SMEM
        for (int idx = tid; idx < 27 * 32 * 9; idx += 256) {
            int oc = idx / 288;
            int rem = idx % 288;
            int c  = rem / 9;
            int kk = rem % 9;
            ws[c * 252 + kk * 28 + oc] = ow[(oc * CIN + c0 + c) * 9 + kk];
        }
        for (int idx = tid; idx < 288; idx += 256) {
            int c = idx / 9, kk = idx % 9;
            ws[c * 252 + kk * 28 + 27] = 0.f;   // pad lane
        }
        __syncthreads();

#pragma unroll 1
        for (int c = 0; c < 32; ++c) {
            const float* xc = x + ((size_t)(b * CIN + c0 + c)) * NPIX;
            float xv[9];
#pragma unroll
            for (int ki = 0; ki < 3; ki++) {
#pragma unroll
                for (int kj = 0; kj < 3; kj++) {
                    bool rok = (ki == 0) ? r0ok : ((ki == 2) ? r2ok : true);
                    bool cok = (kj == 0) ? c0ok : ((kj == 2) ? c2ok : true);
                    int yy = ho - 1 + ki, xx = wo - 1 + kj;
                    xv[ki * 3 + kj] = (rok && cok) ? xc[yy * 64 + xx] : 0.f;
                }
            }
#pragma unroll
            for (int kk = 0; kk < 9; kk++) {
                float xvk = xv[kk];
                const float4* wrow =
                    reinterpret_cast<const float4*>(&ws[c * 252 + kk * 28]);
#pragma unroll
                for (int o4 = 0; o4 < 7; o4++) {
                    float4 w = wrow[o4];
                    acc[o4 * 4 + 0] += xvk * w.x;
                    acc[o4 * 4 + 1] += xvk * w.y;
                    acc[o4 * 4 + 2] += xvk * w.z;
                    acc[o4 * 4 + 3] += xvk * w.w;
                }
            }
        }
    }

    // epilogue: offsets + sigmoid mask + base sampling positions
#pragma unroll
    for (int kk = 0; kk < 9; kk++) {
        float dy = acc[2 * kk]     + ob[2 * kk];
        float dx = acc[2 * kk + 1] + ob[2 * kk + 1];
        float mv = acc[18 + kk]    + ob[18 + kk];
        mv = 1.f / (1.f + __expf(-mv));
        int ki = kk / 3, kj = kk % 3;
        float pyv = dy + (float)(ho - 1 + ki);
        float pxv = dx + (float)(wo - 1 + kj);
        int o = ((b * 9 + kk) << 12) + p;
        g_py[o] = pyv;
        g_px[o] = pxv;
        g_pm[o] = mv;
    }
}

// ===========================================================================
// Kernel 2: bilinear gather -> A[k = c*9+kk][m]  (K-major, coalesced in m)
// ===========================================================================
__global__ __launch_bounds__(256) void gather_kernel(const float* __restrict__ x)
{
    const int tid = threadIdx.x;
    const int m   = blockIdx.x * 256 + tid;
    const int kk  = blockIdx.y;
    const int b   = m >> 12;
    const int p   = m & 4095;

    const int o = ((b * 9 + kk) << 12) + p;
    const float pyv = g_py[o];
    const float pxv = g_px[o];
    const float mv  = g_pm[o];

    float y0f = floorf(pyv), x0f = floorf(pxv);
    float wy1 = pyv - y0f, wx1 = pxv - x0f;
    float wy0 = 1.f - wy1, wx0 = 1.f - wx1;
    int y0 = (int)y0f, x0 = (int)x0f;
    int y1 = y0 + 1,   x1 = x0 + 1;

    float w00 = wy0 * wx0 * mv, w01 = wy0 * wx1 * mv;
    float w10 = wy1 * wx0 * mv, w11 = wy1 * wx1 * mv;
    if (y0 < 0 || y0 > 63) { w00 = 0.f; w01 = 0.f; }
    if (y1 < 0 || y1 > 63) { w10 = 0.f; w11 = 0.f; }
    if (x0 < 0 || x0 > 63) { w00 = 0.f; w10 = 0.f; }
    if (x1 < 0 || x1 > 63) { w01 = 0.f; w11 = 0.f; }

    int y0c = min(max(y0, 0), 63), y1c = min(max(y1, 0), 63);
    int x0c = min(max(x0, 0), 63), x1c = min(max(x1, 0), 63);
    const int o00 = y0c * 64 + x0c, o01 = y0c * 64 + x1c;
    const int o10 = y1c * 64 + x0c, o11 = y1c * 64 + x1c;

    const float* xb = x + (size_t)b * CIN * NPIX;
    float* Ap = g_A + (size_t)kk * MTOT + m;

#pragma unroll 4
    for (int c = 0; c < CIN; ++c) {
        const float* xc = xb + (size_t)c * NPIX;
        float v = w00 * xc[o00] + w01 * xc[o01] +
                  w10 * xc[o10] + w11 * xc[o11];
        Ap[(size_t)c * 9 * MTOT] = v;
    }
}

// ===========================================================================
// Kernel 3: GEMM  out[m][n] = sum_k A[k][m] * W[n][k]  + bias[n]
//   BM=128, BN=128, BK=16, 256 threads, 8x8 microtile via fma.rn.f32x2.
//   A staged into SMEM pre-duplicated {v,v} so the M-operand of FFMA2 needs
//   no in-loop packing.
// ===========================================================================
__global__ __launch_bounds__(256) void gemm_kernel(
    const float* __restrict__ Wt,     // weight [256][2304]
    const float* __restrict__ bias,
    float* __restrict__ out)
{
    const int tid = threadIdx.x;
    const int tx  = tid & 15;          // n dim
    const int ty  = tid >> 4;          // m dim
    const int mBase = blockIdx.x * 128;
    const int nBase = blockIdx.y * 128;

    __shared__ __align__(16) float2 As2[16][128];   // 16 KB (duplicated)
    __shared__ __align__(16) float  Bs [16][128];   //  8 KB

    // staging index precompute
    const int ar   = tid >> 4;         // k row 0..15
    const int aseg = tid & 15;         // m segment (8 floats)
    const int bn   = tid >> 1;         // n row 0..127
    const int bh   = tid & 1;          // k half (8 floats)

    const float* gA = g_A + (size_t)ar * MTOT + mBase + aseg * 8;
    const float* gB = Wt + (size_t)(nBase + bn) * KDIM + bh * 8;

    float4 aR0, aR1, bR0, bR1;
    // prefetch tile 0
    aR0 = *reinterpret_cast<const float4*>(gA);
    aR1 = *reinterpret_cast<const float4*>(gA + 4);
    bR0 = *reinterpret_cast<const float4*>(gB);
    bR1 = *reinterpret_cast<const float4*>(gB + 4);

    ULL acc[8][4];
#pragma unroll
    for (int i = 0; i < 8; i++)
#pragma unroll
        for (int j = 0; j < 4; j++) acc[i][j] = 0ULL;

    const int NK = KDIM / 16;   // 144
    for (int kt = 0; kt < NK; ++kt) {
        __syncthreads();
        // regs -> smem
        {
            float av[8] = {aR0.x, aR0.y, aR0.z, aR0.w, aR1.x, aR1.y, aR1.z, aR1.w};
#pragma unroll
            for (int i = 0; i < 8; i++)
                As2[ar][aseg * 8 + i] = make_float2(av[i], av[i]);
            float bv[8] = {bR0.x, bR0.y, bR0.z, bR0.w, bR1.x, bR1.y, bR1.z, bR1.w};
#pragma unroll
            for (int i = 0; i < 8; i++)
                Bs[bh * 8 + i][bn] = bv[i];
        }
        __syncthreads();

        // prefetch next tile
        if (kt + 1 < NK) {
            const float* nA = gA + (size_t)(kt + 1) * 16 * MTOT;
            const float* nB = gB + (kt + 1) * 16;
            aR0 = *reinterpret_cast<const float4*>(nA);
            aR1 = *reinterpret_cast<const float4*>(nA + 4);
            bR0 = *reinterpret_cast<const float4*>(nB);
            bR1 = *reinterpret_cast<const float4*>(nB + 4);
        }

        // compute
#pragma unroll
        for (int kk = 0; kk < 16; ++kk) {
            const float4* arow = reinterpret_cast<const float4*>(As2[kk]);
            float4 a0 = arow[ty * 4 + 0];
            float4 a1 = arow[ty * 4 + 1];
            float4 a2 = arow[ty * 4 + 2];
            float4 a3 = arow[ty * 4 + 3];
            ULL am[8];
            am[0] = pack2(a0.x, a0.y); am[1] = pack2(a0.z, a0.w);
            am[2] = pack2(a1.x, a1.y); am[3] = pack2(a1.z, a1.w);
            am[4] = pack2(a2.x, a2.y); am[5] = pack2(a2.z, a2.w);
            am[6] = pack2(a3.x, a3.y); am[7] = pack2(a3.z, a3.w);

            const float4* brow = reinterpret_cast<const float4*>(Bs[kk]);
            float4 b0 = brow[tx * 2 + 0];
            float4 b1 = brow[tx * 2 + 1];
            ULL bp[4];
            bp[0] = pack2(b0.x, b0.y); bp[1] = pack2(b0.z, b0.w);
            bp[2] = pack2(b1.x, b1.y); bp[3] = pack2(b1.z, b1.w);

#pragma unroll
            for (int i = 0; i < 8; i++)
#pragma unroll
                for (int j = 0; j < 4; j++)
                    ffma2(acc[i][j], am[i], bp[j]);
        }
    }

    // epilogue: out[b][n][p] = acc + bias[n]
    const int m0   = mBase + ty * 8;
    const int n0   = nBase + tx * 8;
    const int bimg = m0 >> 12;
    const int pb   = m0 & 4095;
    float* ob = out + (size_t)bimg * COUT * NPIX;

    float bv[8];
#pragma unroll
    for (int j = 0; j < 8; j++) bv[j] = bias[n0 + j];

#pragma unroll
    for (int i = 0; i < 8; i++) {
#pragma unroll
        for (int j = 0; j < 4; j++) {
            float v0, v1;
            unpack2(acc[i][j], v0, v1);
            int n = n0 + 2 * j;
            ob[(size_t)n * NPIX + pb + i]       = v0 + bv[2 * j];
            ob[(size_t)(n + 1) * NPIX + pb + i] = v1 + bv[2 * j + 1];
        }
    }
}

// ===========================================================================
extern "C" void kernel_launch(void* const* d_in, const int* in_sizes, int n_in,
                              void* d_out, int out_size)
{
    const float* x        = (const float*)d_in[0];
    const float* weight   = (const float*)d_in[1];
    const float* bias     = (const float*)d_in[2];
    const float* offset_w = (const float*)d_in[3];
    const float* offset_b = (const float*)d_in[4];
    float* out = (float*)d_out;

    // 1) offset conv -> py/px/mask
    offset_conv_kernel<<<MTOT / 256, 256>>>(x, offset_w, offset_b);

    // 2) bilinear gather -> A matrix (K-major)
    dim3 ggrid(MTOT / 256, KKN);
    gather_kernel<<<ggrid, 256>>>(x);

    // 3) implicit GEMM + bias
    dim3 mgrid(MTOT / 128, COUT / 128);
    gemm_kernel<<<mgrid, 256>>>(weight, bias, out);
}

// round 5
// speedup vs baseline: 1.8109x; 1.8109x over previous
#include <cuda_runtime.h>
#include <cuda_bf16.h>
#include <cstdint>

// ---------------------------------------------------------------------------
// DCNv2: B=8, Cin=Cout=256, H=W=64, K=3, S=1, P=1, D=1
// Inputs: x[8,256,64,64], weight[256,256,3,3], bias[256],
//         offset_w[27,256,3,3], offset_b[27]
// Output: [8,256,64,64] fp32
//
// Pipeline:
//   0) wsplit:        weight -> Whi/Wlo (bf16 split), [cout][k=cin*9]
//   1) offset_partial: 4 channel-slices of the 3x3 offset conv -> g_om4
//   2) offset_final:   sum slices + bias, sigmoid mask, sampling positions
//   3) gather:         bilinear sample * mask -> A matrix as bf16 hi/lo,
//                      K-major: g_Ahi/g_Alo[k][m]
//   4) gemm:           out[cout][m] = sum_k W[cout][k]*A[k][m] via
//                      mma.sync m16n8k16 bf16, 3-term compensated split
// ---------------------------------------------------------------------------

#define BDIM   8
#define CIN    256
#define COUT   256
#define KKN    9
#define NPIX   4096
#define MTOT   32768
#define KDIM   2304

// ------------------------- scratch (device globals) ------------------------
__device__ float g_py[BDIM * KKN * NPIX];
__device__ float g_px[BDIM * KKN * NPIX];
__device__ float g_pm[BDIM * KKN * NPIX];
__device__ float g_om4[4 * 27 * MTOT];                    // partial offset conv
__device__ __nv_bfloat16 g_Ahi[(size_t)KDIM * MTOT];      // 151 MB
__device__ __nv_bfloat16 g_Alo[(size_t)KDIM * MTOT];      // 151 MB
__device__ __nv_bfloat16 g_Whi[COUT * KDIM];
__device__ __nv_bfloat16 g_Wlo[COUT * KDIM];

// ------------------------- mma / ldmatrix wrappers -------------------------
static __device__ __forceinline__ uint32_t smem_u32(const void* p) {
    return (uint32_t)__cvta_generic_to_shared(p);
}
static __device__ __forceinline__ void ldsm_x4(uint32_t& r0, uint32_t& r1,
                                               uint32_t& r2, uint32_t& r3,
                                               uint32_t addr) {
    asm volatile("ldmatrix.sync.aligned.m8n8.x4.shared.b16 {%0,%1,%2,%3}, [%4];"
                 : "=r"(r0), "=r"(r1), "=r"(r2), "=r"(r3) : "r"(addr));
}
static __device__ __forceinline__ void ldsm_x4_t(uint32_t& r0, uint32_t& r1,
                                                 uint32_t& r2, uint32_t& r3,
                                                 uint32_t addr) {
    asm volatile("ldmatrix.sync.aligned.m8n8.x4.trans.shared.b16 {%0,%1,%2,%3}, [%4];"
                 : "=r"(r0), "=r"(r1), "=r"(r2), "=r"(r3) : "r"(addr));
}
static __device__ __forceinline__ void mma_bf16(float* d, const uint32_t* a,
                                                uint32_t b0, uint32_t b1) {
    asm volatile(
        "mma.sync.aligned.m16n8k16.row.col.f32.bf16.bf16.f32 "
        "{%0,%1,%2,%3},{%4,%5,%6,%7},{%8,%9},{%0,%1,%2,%3};"
        : "+f"(d[0]), "+f"(d[1]), "+f"(d[2]), "+f"(d[3])
        : "r"(a[0]), "r"(a[1]), "r"(a[2]), "r"(a[3]), "r"(b0), "r"(b1));
}

// ===========================================================================
// Kernel 0: weight bf16 hi/lo split
// ===========================================================================
__global__ __launch_bounds__(256) void wsplit_kernel(const float* __restrict__ w)
{
    int i = blockIdx.x * 256 + threadIdx.x;
    if (i < COUT * KDIM) {
        float v = w[i];
        __nv_bfloat16 h = __float2bfloat16(v);
        float hf = __bfloat162float(h);
        g_Whi[i] = h;
        g_Wlo[i] = __float2bfloat16(v - hf);
    }
}

// ===========================================================================
// Kernel 1: offset conv partial (one 64-channel slice per blockIdx.y)
// ===========================================================================
__global__ __launch_bounds__(256) void offset_partial_kernel(
    const float* __restrict__ x,
    const float* __restrict__ ow)
{
    const int tid = threadIdx.x;
    const int m   = blockIdx.x * 256 + tid;
    const int sl  = blockIdx.y;                 // channel slice 0..3
    const int b   = m >> 12;
    const int p   = m & 4095;
    const int ho  = p >> 6;
    const int wo  = p & 63;

    __shared__ __align__(16) float ws[32 * 9 * 28];

    float acc[28];
#pragma unroll
    for (int i = 0; i < 28; i++) acc[i] = 0.f;

    const bool r0ok = (ho > 0), r2ok = (ho < 63);
    const bool c0ok = (wo > 0), c2ok = (wo < 63);

    for (int it = 0; it < 2; ++it) {
        const int c0 = sl * 64 + it * 32;
        __syncthreads();
        for (int idx = tid; idx < 27 * 32 * 9; idx += 256) {
            int oc  = idx / 288;
            int rem = idx % 288;
            int c   = rem / 9;
            int kk  = rem % 9;
            ws[c * 252 + kk * 28 + oc] = ow[(oc * CIN + c0 + c) * 9 + kk];
        }
        for (int idx = tid; idx < 288; idx += 256) {
            int c = idx / 9, kk = idx % 9;
            ws[c * 252 + kk * 28 + 27] = 0.f;
        }
        __syncthreads();

#pragma unroll 1
        for (int c = 0; c < 32; ++c) {
            const float* xc = x + ((size_t)(b * CIN + c0 + c)) * NPIX;
            float xv[9];
#pragma unroll
            for (int ki = 0; ki < 3; ki++) {
#pragma unroll
                for (int kj = 0; kj < 3; kj++) {
                    bool rok = (ki == 0) ? r0ok : ((ki == 2) ? r2ok : true);
                    bool cok = (kj == 0) ? c0ok : ((kj == 2) ? c2ok : true);
                    int yy = ho - 1 + ki, xx = wo - 1 + kj;
                    xv[ki * 3 + kj] = (rok && cok) ? xc[yy * 64 + xx] : 0.f;
                }
            }
#pragma unroll
            for (int kk = 0; kk < 9; kk++) {
                float xvk = xv[kk];
                const float4* wrow =
                    reinterpret_cast<const float4*>(&ws[c * 252 + kk * 28]);
#pragma unroll
                for (int o4 = 0; o4 < 7; o4++) {
                    float4 w = wrow[o4];
                    acc[o4 * 4 + 0] += xvk * w.x;
                    acc[o4 * 4 + 1] += xvk * w.y;
                    acc[o4 * 4 + 2] += xvk * w.z;
                    acc[o4 * 4 + 3] += xvk * w.w;
                }
            }
        }
    }

#pragma unroll
    for (int i = 0; i < 27; i++)
        g_om4[((size_t)(sl * 27 + i)) * MTOT + m] = acc[i];
}

// ===========================================================================
// Kernel 2: offset finalize -> py / px / mask
// ===========================================================================
__global__ __launch_bounds__(256) void offset_final_kernel(
    const float* __restrict__ ob)
{
    const int m  = blockIdx.x * 256 + threadIdx.x;
    const int b  = m >> 12;
    const int p  = m & 4095;
    const int ho = p >> 6;
    const int wo = p & 63;

    float acc[27];
#pragma unroll
    for (int i = 0; i < 27; i++) {
        float s = 0.f;
#pragma unroll
        for (int sl = 0; sl < 4; sl++)
            s += g_om4[((size_t)(sl * 27 + i)) * MTOT + m];
        acc[i] = s;
    }

#pragma unroll
    for (int kk = 0; kk < 9; kk++) {
        float dy = acc[2 * kk]     + ob[2 * kk];
        float dx = acc[2 * kk + 1] + ob[2 * kk + 1];
        float mv = acc[18 + kk]    + ob[18 + kk];
        mv = 1.f / (1.f + __expf(-mv));
        int ki = kk / 3, kj = kk % 3;
        float pyv = dy + (float)(ho - 1 + ki);
        float pxv = dx + (float)(wo - 1 + kj);
        int o = ((b * 9 + kk) << 12) + p;
        g_py[o] = pyv;
        g_px[o] = pxv;
        g_pm[o] = mv;
    }
}

// ===========================================================================
// Kernel 3: bilinear gather -> A matrix as bf16 hi/lo, K-major g_A*[k][m]
// ===========================================================================
__global__ __launch_bounds__(256) void gather_kernel(const float* __restrict__ x)
{
    const int tid = threadIdx.x;
    const int m   = blockIdx.x * 256 + tid;
    const int kk  = blockIdx.y;
    const int b   = m >> 12;
    const int p   = m & 4095;

    const int o = ((b * 9 + kk) << 12) + p;
    const float pyv = g_py[o];
    const float pxv = g_px[o];
    const float mv  = g_pm[o];

    float y0f = floorf(pyv), x0f = floorf(pxv);
    float wy1 = pyv - y0f, wx1 = pxv - x0f;
    float wy0 = 1.f - wy1, wx0 = 1.f - wx1;
    int y0 = (int)y0f, x0 = (int)x0f;
    int y1 = y0 + 1,   x1 = x0 + 1;

    float w00 = wy0 * wx0 * mv, w01 = wy0 * wx1 * mv;
    float w10 = wy1 * wx0 * mv, w11 = wy1 * wx1 * mv;
    if (y0 < 0 || y0 > 63) { w00 = 0.f; w01 = 0.f; }
    if (y1 < 0 || y1 > 63) { w10 = 0.f; w11 = 0.f; }
    if (x0 < 0 || x0 > 63) { w00 = 0.f; w10 = 0.f; }
    if (x1 < 0 || x1 > 63) { w01 = 0.f; w11 = 0.f; }

    int y0c = min(max(y0, 0), 63), y1c = min(max(y1, 0), 63);
    int x0c = min(max(x0, 0), 63), x1c = min(max(x1, 0), 63);
    const int o00 = y0c * 64 + x0c, o01 = y0c * 64 + x1c;
    const int o10 = y1c * 64 + x0c, o11 = y1c * 64 + x1c;

    const float* xb = x + (size_t)b * CIN * NPIX;
    const size_t base = (size_t)kk * MTOT + m;

#pragma unroll 4
    for (int c = 0; c < CIN; ++c) {
        const float* xc = xb + (size_t)c * NPIX;
        float v = w00 * xc[o00] + w01 * xc[o01] +
                  w10 * xc[o10] + w11 * xc[o11];
        __nv_bfloat16 h = __float2bfloat16(v);
        float hf = __bfloat162float(h);
        __nv_bfloat16 l = __float2bfloat16(v - hf);
        size_t idx = base + (size_t)c * 9 * MTOT;   // k = c*9 + kk
        g_Ahi[idx] = h;
        g_Alo[idx] = l;
    }
}

// ===========================================================================
// Kernel 4: tensor-core GEMM  out[cout][m] = sum_k W[cout][k] * A[k][m]
//   Block tile: 128 cout x 128 pixels x k16.  256 threads = 8 warps (2x4).
//   Warp tile: 64 cout x 32 pixels.  3-term bf16 split per k16:
//     acc += Ahi*Bhi + Ahi*Blo + Alo*Bhi
//   SMEM:
//     As: 128 rows(m=cout) x 80B  ([16 hi bf16][16 lo bf16][16B pad])
//     Bs: hi/lo each 16 rows(k) x 256B, chunk-XOR swizzled
// ===========================================================================
__global__ __launch_bounds__(256, 1) void gemm_kernel(
    const float* __restrict__ bias,
    float* __restrict__ out)
{
    const int tid  = threadIdx.x;
    const int warp = tid >> 5;
    const int lane = tid & 31;
    const int mBase    = blockIdx.x * 128;   // pixel base
    const int coutBase = blockIdx.y * 128;

    __shared__ __align__(16) unsigned char AsB[128 * 80];   // 10240 B
    __shared__ __align__(16) unsigned char BsHiB[16 * 256]; //  4096 B
    __shared__ __align__(16) unsigned char BsLoB[16 * 256]; //  4096 B

    // ------ staging indices ------
    const int am   = tid >> 1;         // A: row (cout within tile) 0..127
    const int ah   = tid & 1;          // A: 0=hi, 1=lo
    const int bk   = tid >> 4;         // B: k row 0..15
    const int bc   = tid & 15;         // B: n-chunk (8 pixels)

    const __nv_bfloat16* gA = (ah ? g_Wlo : g_Whi) +
                              (size_t)(coutBase + am) * KDIM;
    const __nv_bfloat16* gBh = g_Ahi + (size_t)bk * MTOT + mBase + bc * 8;
    const __nv_bfloat16* gBl = g_Alo + (size_t)bk * MTOT + mBase + bc * 8;

    uint4 aR0, aR1, bRh, bRl;
    // prefetch chunk 0
    aR0 = *reinterpret_cast<const uint4*>(gA);
    aR1 = *reinterpret_cast<const uint4*>(gA + 8);
    bRh = *reinterpret_cast<const uint4*>(gBh);
    bRl = *reinterpret_cast<const uint4*>(gBl);

    // ------ fragment addresses (per lane) ------
    const int wm = (warp >> 2) * 64;   // warp cout offset
    const int wn = (warp & 3) * 32;    // warp pixel offset

    // A ldmatrix: row = wm + mi*16 + (lane&15), +16B if lane>=16 (k8..15)
    uint32_t aAddrBase = smem_u32(AsB) +
        (uint32_t)((wm + (lane & 15)) * 80 + ((lane >> 4) & 1) * 16);
    // B ldmatrix.trans: kRow = (lane&7) + ((lane>>3)&1)*8 ; chunk = base + ((lane>>4)&1)
    const int kRow   = (lane & 7) + ((lane >> 3) & 1) * 8;
    const int chBase = (wn >> 3) + ((lane >> 4) & 1);
    uint32_t bOffHi = (uint32_t)(kRow * 256);
    uint32_t sBsHi = smem_u32(BsHiB);
    uint32_t sBsLo = smem_u32(BsLoB);

    float acc[4][4][4];
#pragma unroll
    for (int i = 0; i < 4; i++)
#pragma unroll
        for (int j = 0; j < 4; j++)
#pragma unroll
            for (int r = 0; r < 4; r++) acc[i][j][r] = 0.f;

    const uint32_t aStDst = smem_u32(AsB) + (uint32_t)(am * 80 + ah * 32);
    const uint32_t bStOff = (uint32_t)(bk * 256 + ((bc ^ (bk & 7)) * 16));

    const int NK = KDIM / 16;   // 144
    for (int kt = 0; kt < NK; ++kt) {
        __syncthreads();
        // regs -> smem
        *reinterpret_cast<uint4*>((unsigned char*)AsB + (am * 80 + ah * 32)) = aR0;
        *reinterpret_cast<uint4*>((unsigned char*)AsB + (am * 80 + ah * 32 + 16)) = aR1;
        *reinterpret_cast<uint4*>(BsHiB + bStOff) = bRh;
        *reinterpret_cast<uint4*>(BsLoB + bStOff) = bRl;
        __syncthreads();

        // prefetch next chunk
        if (kt + 1 < NK) {
            const __nv_bfloat16* nA = gA + (kt + 1) * 16;
            aR0 = *reinterpret_cast<const uint4*>(nA);
            aR1 = *reinterpret_cast<const uint4*>(nA + 8);
            const size_t bstep = (size_t)(kt + 1) * 16 * MTOT;
            bRh = *reinterpret_cast<const uint4*>(gBh + bstep);
            bRl = *reinterpret_cast<const uint4*>(gBl + bstep);
        }

        // ---- load fragments ----
        uint32_t ahi[4][4], alo[4][4];
#pragma unroll
        for (int mi = 0; mi < 4; mi++) {
            uint32_t ad = aAddrBase + (uint32_t)(mi * 16 * 80);
            ldsm_x4(ahi[mi][0], ahi[mi][1], ahi[mi][2], ahi[mi][3], ad);
            ldsm_x4(alo[mi][0], alo[mi][1], alo[mi][2], alo[mi][3], ad + 32);
        }
        uint32_t bhi[2][4], blo[2][4];
#pragma unroll
        for (int nj = 0; nj < 2; nj++) {
            uint32_t ch = (uint32_t)(((chBase + nj * 2) ^ (kRow & 7)) * 16);
            ldsm_x4_t(bhi[nj][0], bhi[nj][1], bhi[nj][2], bhi[nj][3],
                      sBsHi + bOffHi + ch);
            ldsm_x4_t(blo[nj][0], blo[nj][1], blo[nj][2], blo[nj][3],
                      sBsLo + bOffHi + ch);
        }

        // ---- 48 mma ----
#pragma unroll
        for (int mi = 0; mi < 4; mi++) {
#pragma unroll
            for (int nj = 0; nj < 2; nj++) {
#pragma unroll
                for (int h = 0; h < 2; h++) {
                    int ni = nj * 2 + h;
                    mma_bf16(acc[mi][ni], ahi[mi], bhi[nj][2*h], bhi[nj][2*h+1]);
                    mma_bf16(acc[mi][ni], ahi[mi], blo[nj][2*h], blo[nj][2*h+1]);
                    mma_bf16(acc[mi][ni], alo[mi], bhi[nj][2*h], bhi[nj][2*h+1]);
                }
            }
        }
    }

    // ---- epilogue ----
    const int g = lane >> 2;          // row-in-16 group
    const int t = lane & 3;           // col pair
    const int b    = mBase >> 12;
    const int pbB  = (mBase & 4095) + wn;
    float* outB = out + (size_t)b * COUT * NPIX;

#pragma unroll
    for (int mi = 0; mi < 4; mi++) {
        int c0 = coutBase + wm + mi * 16 + g;
        int c1 = c0 + 8;
        float bv0 = __ldg(&bias[c0]);
        float bv1 = __ldg(&bias[c1]);
        float* r0 = outB + (size_t)c0 * NPIX + pbB;
        float* r1 = outB + (size_t)c1 * NPIX + pbB;
#pragma unroll
        for (int ni = 0; ni < 4; ni++) {
            int pcol = ni * 8 + 2 * t;
            float2 v0 = make_float2(acc[mi][ni][0] + bv0, acc[mi][ni][1] + bv0);
            float2 v1 = make_float2(acc[mi][ni][2] + bv1, acc[mi][ni][3] + bv1);
            *reinterpret_cast<float2*>(r0 + pcol) = v0;
            *reinterpret_cast<float2*>(r1 + pcol) = v1;
        }
    }
}

// ===========================================================================
extern "C" void kernel_launch(void* const* d_in, const int* in_sizes, int n_in,
                              void* d_out, int out_size)
{
    const float* x        = (const float*)d_in[0];
    const float* weight   = (const float*)d_in[1];
    const float* bias     = (const float*)d_in[2];
    const float* offset_w = (const float*)d_in[3];
    const float* offset_b = (const float*)d_in[4];
    float* out = (float*)d_out;

    // 0) weight hi/lo split
    wsplit_kernel<<<(COUT * KDIM + 255) / 256, 256>>>(weight);

    // 1) offset conv partials (4 channel slices)
    dim3 ogrid(MTOT / 256, 4);
    offset_partial_kernel<<<ogrid, 256>>>(x, offset_w);

    // 2) finalize offsets
    offset_final_kernel<<<MTOT / 256, 256>>>(offset_b);

    // 3) bilinear gather -> bf16 hi/lo A matrix
    dim3 ggrid(MTOT / 256, KKN);
    gather_kernel<<<ggrid, 256>>>(x);

    // 4) tensor-core GEMM + bias
    dim3 mgrid(MTOT / 128, COUT / 128);
    gemm_kernel<<<mgrid, 256>>>(bias, out);
}

// round 7
// speedup vs baseline: 2.2316x; 1.2323x over previous
#include <cuda_runtime.h>
#include <cuda_bf16.h>
#include <cstdint>

// ---------------------------------------------------------------------------
// DCNv2: B=8, Cin=Cout=256, H=W=64, K=3, S=1, P=1, D=1
// Pipeline:
//   0) wsplit:         weight -> Whi/Wlo (bf16 split), [cout][k]
//   1) offset_partial: 4 channel-slices of 3x3 offset conv -> g_om4
//   2) offset_final:   sum + bias, sigmoid mask, sampling positions
//   3) gather:         bilinear sample * mask -> A bf16 hi/lo, K-major [k][m]
//   4) gemm:           mma.sync m16n8k16 bf16, 3-term compensated split,
//                      cp.async 6-stage pipeline, term-major mma order
// (tcgen05 is NOT available: harness PTX target is compute_103, no 'a' feats)
// ---------------------------------------------------------------------------

#define BDIM   8
#define CIN    256
#define COUT   256
#define KKN    9
#define NPIX   4096
#define MTOT   32768
#define KDIM   2304

// ------------------------- scratch (device globals) ------------------------
__device__ float g_py[BDIM * KKN * NPIX];
__device__ float g_px[BDIM * KKN * NPIX];
__device__ float g_pm[BDIM * KKN * NPIX];
__device__ float g_om4[4 * 27 * MTOT];
__device__ __nv_bfloat16 g_Ahi[(size_t)KDIM * MTOT];   // [k][m]
__device__ __nv_bfloat16 g_Alo[(size_t)KDIM * MTOT];
__device__ __nv_bfloat16 g_Whi[COUT * KDIM];           // [n][k]
__device__ __nv_bfloat16 g_Wlo[COUT * KDIM];

// ------------------------- PTX wrappers ------------------------------------
static __device__ __forceinline__ uint32_t smem_u32(const void* p) {
    return (uint32_t)__cvta_generic_to_shared(p);
}
static __device__ __forceinline__ void ldsm_x4(uint32_t& r0, uint32_t& r1,
                                               uint32_t& r2, uint32_t& r3,
                                               uint32_t addr) {
    asm volatile("ldmatrix.sync.aligned.m8n8.x4.shared.b16 {%0,%1,%2,%3}, [%4];"
                 : "=r"(r0), "=r"(r1), "=r"(r2), "=r"(r3) : "r"(addr));
}
static __device__ __forceinline__ void ldsm_x4_t(uint32_t& r0, uint32_t& r1,
                                                 uint32_t& r2, uint32_t& r3,
                                                 uint32_t addr) {
    asm volatile("ldmatrix.sync.aligned.m8n8.x4.trans.shared.b16 {%0,%1,%2,%3}, [%4];"
                 : "=r"(r0), "=r"(r1), "=r"(r2), "=r"(r3) : "r"(addr));
}
static __device__ __forceinline__ void mma_bf16(float* d, const uint32_t* a,
                                                uint32_t b0, uint32_t b1) {
    asm volatile(
        "mma.sync.aligned.m16n8k16.row.col.f32.bf16.bf16.f32 "
        "{%0,%1,%2,%3},{%4,%5,%6,%7},{%8,%9},{%0,%1,%2,%3};"
        : "+f"(d[0]), "+f"(d[1]), "+f"(d[2]), "+f"(d[3])
        : "r"(a[0]), "r"(a[1]), "r"(a[2]), "r"(a[3]), "r"(b0), "r"(b1));
}
static __device__ __forceinline__ void cpasync16(uint32_t dst, const void* src) {
    asm volatile("cp.async.cg.shared.global [%0], [%1], 16;"
                 :: "r"(dst), "l"(src) : "memory");
}
static __device__ __forceinline__ void cp_commit() {
    asm volatile("cp.async.commit_group;" ::: "memory");
}
static __device__ __forceinline__ void cp_wait4() {
    asm volatile("cp.async.wait_group 4;" ::: "memory");
}

// ===========================================================================
// Kernel 0: weight bf16 hi/lo split
// ===========================================================================
__global__ __launch_bounds__(256) void wsplit_kernel(const float* __restrict__ w)
{
    int i = blockIdx.x * 256 + threadIdx.x;
    if (i < COUT * KDIM) {
        float v = w[i];
        __nv_bfloat16 h = __float2bfloat16(v);
        float hf = __bfloat162float(h);
        g_Whi[i] = h;
        g_Wlo[i] = __float2bfloat16(v - hf);
    }
}

// ===========================================================================
// Kernel 1: offset conv partial (one 64-channel slice per blockIdx.y)
// ===========================================================================
__global__ __launch_bounds__(256) void offset_partial_kernel(
    const float* __restrict__ x,
    const float* __restrict__ ow)
{
    const int tid = threadIdx.x;
    const int m   = blockIdx.x * 256 + tid;
    const int sl  = blockIdx.y;
    const int b   = m >> 12;
    const int p   = m & 4095;
    const int ho  = p >> 6;
    const int wo  = p & 63;

    __shared__ __align__(16) float ws[32 * 9 * 28];

    float acc[28];
#pragma unroll
    for (int i = 0; i < 28; i++) acc[i] = 0.f;

    const bool r0ok = (ho > 0), r2ok = (ho < 63);
    const bool c0ok = (wo > 0), c2ok = (wo < 63);

    for (int it = 0; it < 2; ++it) {
        const int c0 = sl * 64 + it * 32;
        __syncthreads();
        for (int idx = tid; idx < 27 * 32 * 9; idx += 256) {
            int oc  = idx / 288;
            int rem = idx % 288;
            int c   = rem / 9;
            int kk  = rem % 9;
            ws[c * 252 + kk * 28 + oc] = ow[(oc * CIN + c0 + c) * 9 + kk];
        }
        for (int idx = tid; idx < 288; idx += 256) {
            int c = idx / 9, kk = idx % 9;
            ws[c * 252 + kk * 28 + 27] = 0.f;
        }
        __syncthreads();

#pragma unroll 1
        for (int c = 0; c < 32; ++c) {
            const float* xc = x + ((size_t)(b * CIN + c0 + c)) * NPIX;
            float xv[9];
#pragma unroll
            for (int ki = 0; ki < 3; ki++) {
#pragma unroll
                for (int kj = 0; kj < 3; kj++) {
                    bool rok = (ki == 0) ? r0ok : ((ki == 2) ? r2ok : true);
                    bool cok = (kj == 0) ? c0ok : ((kj == 2) ? c2ok : true);
                    int yy = ho - 1 + ki, xx = wo - 1 + kj;
                    xv[ki * 3 + kj] = (rok && cok) ? xc[yy * 64 + xx] : 0.f;
                }
            }
#pragma unroll
            for (int kk = 0; kk < 9; kk++) {
                float xvk = xv[kk];
                const float4* wrow =
                    reinterpret_cast<const float4*>(&ws[c * 252 + kk * 28]);
#pragma unroll
                for (int o4 = 0; o4 < 7; o4++) {
                    float4 w = wrow[o4];
                    acc[o4 * 4 + 0] += xvk * w.x;
                    acc[o4 * 4 + 1] += xvk * w.y;
                    acc[o4 * 4 + 2] += xvk * w.z;
                    acc[o4 * 4 + 3] += xvk * w.w;
                }
            }
        }
    }

#pragma unroll
    for (int i = 0; i < 27; i++)
        g_om4[((size_t)(sl * 27 + i)) * MTOT + m] = acc[i];
}

// ===========================================================================
// Kernel 2: offset finalize -> py / px / mask
// ===========================================================================
__global__ __launch_bounds__(256) void offset_final_kernel(
    const float* __restrict__ ob)
{
    const int m  = blockIdx.x * 256 + threadIdx.x;
    const int b  = m >> 12;
    const int p  = m & 4095;
    const int ho = p >> 6;
    const int wo = p & 63;

    float acc[27];
#pragma unroll
    for (int i = 0; i < 27; i++) {
        float s = 0.f;
#pragma unroll
        for (int sl = 0; sl < 4; sl++)
            s += g_om4[((size_t)(sl * 27 + i)) * MTOT + m];
        acc[i] = s;
    }

#pragma unroll
    for (int kk = 0; kk < 9; kk++) {
        float dy = acc[2 * kk]     + ob[2 * kk];
        float dx = acc[2 * kk + 1] + ob[2 * kk + 1];
        float mv = acc[18 + kk]    + ob[18 + kk];
        mv = 1.f / (1.f + __expf(-mv));
        int ki = kk / 3, kj = kk % 3;
        float pyv = dy + (float)(ho - 1 + ki);
        float pxv = dx + (float)(wo - 1 + kj);
        int o = ((b * 9 + kk) << 12) + p;
        g_py[o] = pyv;
        g_px[o] = pxv;
        g_pm[o] = mv;
    }
}

// ===========================================================================
// Kernel 3: bilinear gather -> A bf16 hi/lo, K-major g_A*[k = c*9+kk][m]
// ===========================================================================
__global__ __launch_bounds__(256) void gather_kernel(const float* __restrict__ x)
{
    const int tid = threadIdx.x;
    const int m   = blockIdx.x * 256 + tid;
    const int kk  = blockIdx.y;
    const int b   = m >> 12;
    const int p   = m & 4095;

    const int o = ((b * 9 + kk) << 12) + p;
    const float pyv = g_py[o];
    const float pxv = g_px[o];
    const float mv  = g_pm[o];

    float y0f = floorf(pyv), x0f = floorf(pxv);
    float wy1 = pyv - y0f, wx1 = pxv - x0f;
    float wy0 = 1.f - wy1, wx0 = 1.f - wx1;
    int y0 = (int)y0f, x0 = (int)x0f;
    int y1 = y0 + 1,   x1 = x0 + 1;

    float w00 = wy0 * wx0 * mv, w01 = wy0 * wx1 * mv;
    float w10 = wy1 * wx0 * mv, w11 = wy1 * wx1 * mv;
    if (y0 < 0 || y0 > 63) { w00 = 0.f; w01 = 0.f; }
    if (y1 < 0 || y1 > 63) { w10 = 0.f; w11 = 0.f; }
    if (x0 < 0 || x0 > 63) { w00 = 0.f; w10 = 0.f; }
    if (x1 < 0 || x1 > 63) { w01 = 0.f; w11 = 0.f; }

    int y0c = min(max(y0, 0), 63), y1c = min(max(y1, 0), 63);
    int x0c = min(max(x0, 0), 63), x1c = min(max(x1, 0), 63);
    const int o00 = y0c * 64 + x0c, o01 = y0c * 64 + x1c;
    const int o10 = y1c * 64 + x0c, o11 = y1c * 64 + x1c;

    const float* xb = x + (size_t)b * CIN * NPIX;
    const size_t base = (size_t)kk * MTOT + m;

#pragma unroll 4
    for (int c = 0; c < CIN; ++c) {
        const float* xc = xb + (size_t)c * NPIX;
        float v = w00 * xc[o00] + w01 * xc[o01] +
                  w10 * xc[o10] + w11 * xc[o11];
        __nv_bfloat16 h = __float2bfloat16(v);
        float hf = __bfloat162float(h);
        __nv_bfloat16 l = __float2bfloat16(v - hf);
        size_t idx = base + (size_t)c * 9 * MTOT;   // k = c*9 + kk
        g_Ahi[idx] = h;
        g_Alo[idx] = l;
    }
}

// ===========================================================================
// Kernel 4: HMMA GEMM  out[cout][m] = sum_k W[cout][k] * A[k][m]
//   Block tile 128 cout x 128 pixels, 8 warps (warp tile 64x32).
//   6-stage cp.async ring (BK=16, 18 KB/stage), one barrier per stage.
//   Per stage, per warp: 48 mma issued TERM-MAJOR (16 independent accs/term).
//   Stage layout: [As 128x80 | BsHi 16x256 | BsLo 16x256]  (R5-verified)
// ===========================================================================
#define NSTG      6
#define STG_BYTES 18432
#define OFF_BHI   10240
#define OFF_BLO   14336
#define GEMM_SMEM (NSTG * STG_BYTES)   // 110592

__global__ __launch_bounds__(256, 1) void gemm_kernel(
    const float* __restrict__ bias,
    float* __restrict__ out)
{
    extern __shared__ __align__(1024) unsigned char smem[];
    const uint32_t sbase = smem_u32(smem);
    const int tid  = threadIdx.x;
    const int warp = tid >> 5;
    const int lane = tid & 31;
    const int mBase    = blockIdx.x * 128;   // pixel base
    const int coutBase = blockIdx.y * 128;

    // ------ staging indices ------
    const int am = tid >> 1;          // A: cout row in tile 0..127
    const int ah = tid & 1;           // A: 0=hi, 1=lo
    const int bk = tid >> 4;          // B: k row 0..15
    const int bc = tid & 15;          // B: pixel chunk (8 bf16)

    const char* gA  = reinterpret_cast<const char*>(
        (ah ? g_Wlo : g_Whi) + (size_t)(coutBase + am) * KDIM);
    const char* gBh = reinterpret_cast<const char*>(
        g_Ahi + (size_t)bk * MTOT + mBase + bc * 8);
    const char* gBl = reinterpret_cast<const char*>(
        g_Alo + (size_t)bk * MTOT + mBase + bc * 8);

    const uint32_t aSts = (uint32_t)(am * 80 + ah * 32);
    const uint32_t bSts = (uint32_t)(bk * 256 + ((bc ^ (bk & 7)) * 16));

    // ------ fragment addresses ------
    const int wm = (warp >> 2) * 64;
    const int wn = (warp & 3) * 32;
    const uint32_t aAddrBase = sbase +
        (uint32_t)((wm + (lane & 15)) * 80 + ((lane >> 4) & 1) * 16);
    const int kRow   = (lane & 7) + ((lane >> 3) & 1) * 8;
    const int chBase = (wn >> 3) + ((lane >> 4) & 1);
    const uint32_t bOff = (uint32_t)(kRow * 256);
    const uint32_t ch0 = (uint32_t)(((chBase + 0) ^ (kRow & 7)) * 16);
    const uint32_t ch1 = (uint32_t)(((chBase + 2) ^ (kRow & 7)) * 16);

    float acc[4][4][4];
#pragma unroll
    for (int i = 0; i < 4; i++)
#pragma unroll
        for (int j = 0; j < 4; j++)
#pragma unroll
            for (int r = 0; r < 4; r++) acc[i][j][r] = 0.f;

    const int NK = KDIM / 16;   // 144

    // ---- issue one stage's cp.asyncs (4 x 16B per thread) ----
    auto issue = [&](int kt, int buf) {
        const uint32_t sb = sbase + (uint32_t)(buf * STG_BYTES);
        const char* sa  = gA  + (size_t)kt * 32;           // 16 bf16 = 32 B
        const char* sbh = gBh + (size_t)kt * 16 * MTOT * 2;
        const char* sbl = gBl + (size_t)kt * 16 * MTOT * 2;
        cpasync16(sb + aSts,          sa);
        cpasync16(sb + aSts + 16,     sa + 16);
        cpasync16(sb + OFF_BHI + bSts, sbh);
        cpasync16(sb + OFF_BLO + bSts, sbl);
        cp_commit();
    };

    // prologue: 5 stages in flight
#pragma unroll
    for (int kt = 0; kt < 5; ++kt) issue(kt, kt);

    for (int kt = 0; kt < NK; ++kt) {
        const int buf = kt % NSTG;
        cp_wait4();            // stage kt complete (per-thread)
        __syncthreads();       // visible to all threads

        const uint32_t stg = (uint32_t)(buf * STG_BYTES);

        // ---- load fragments ----
        uint32_t ahi[4][4], alo[4][4];
#pragma unroll
        for (int mi = 0; mi < 4; mi++) {
            uint32_t ad = aAddrBase + stg + (uint32_t)(mi * 16 * 80);
            ldsm_x4(ahi[mi][0], ahi[mi][1], ahi[mi][2], ahi[mi][3], ad);
            ldsm_x4(alo[mi][0], alo[mi][1], alo[mi][2], alo[mi][3], ad + 32);
        }
        uint32_t bhi[2][4], blo[2][4];
        {
            const uint32_t hbase = sbase + OFF_BHI + stg + bOff;
            const uint32_t lbase = sbase + OFF_BLO + stg + bOff;
            ldsm_x4_t(bhi[0][0], bhi[0][1], bhi[0][2], bhi[0][3], hbase + ch0);
            ldsm_x4_t(bhi[1][0], bhi[1][1], bhi[1][2], bhi[1][3], hbase + ch1);
            ldsm_x4_t(blo[0][0], blo[0][1], blo[0][2], blo[0][3], lbase + ch0);
            ldsm_x4_t(blo[1][0], blo[1][1], blo[1][2], blo[1][3], lbase + ch1);
        }

        // refill the ring (buffer consumed in iteration kt-1)
        if (kt + 5 < NK) issue(kt + 5, (kt + 5) % NSTG);
        else             cp_commit();   // empty group keeps wait_group math exact

        // ---- 48 mma, term-major (16 independent accumulators per sweep) ----
#pragma unroll
        for (int mi = 0; mi < 4; mi++)
#pragma unroll
            for (int nj = 0; nj < 2; nj++)
#pragma unroll
                for (int h = 0; h < 2; h++)
                    mma_bf16(acc[mi][nj * 2 + h], ahi[mi],
                             bhi[nj][2 * h], bhi[nj][2 * h + 1]);
#pragma unroll
        for (int mi = 0; mi < 4; mi++)
#pragma unroll
            for (int nj = 0; nj < 2; nj++)
#pragma unroll
                for (int h = 0; h < 2; h++)
                    mma_bf16(acc[mi][nj * 2 + h], ahi[mi],
                             blo[nj][2 * h], blo[nj][2 * h + 1]);
#pragma unroll
        for (int mi = 0; mi < 4; mi++)
#pragma unroll
            for (int nj = 0; nj < 2; nj++)
#pragma unroll
                for (int h = 0; h < 2; h++)
                    mma_bf16(acc[mi][nj * 2 + h], alo[mi],
                             bhi[nj][2 * h], bhi[nj][2 * h + 1]);

        __syncthreads();   // all warps done with buffer before next refill cycle
    }

    // ---- epilogue ----
    const int g = lane >> 2;
    const int t = lane & 3;
    const int b    = mBase >> 12;
    const int pbB  = (mBase & 4095) + wn;
    float* outB = out + (size_t)b * COUT * NPIX;

#pragma unroll
    for (int mi = 0; mi < 4; mi++) {
        int c0 = coutBase + wm + mi * 16 + g;
        int c1 = c0 + 8;
        float bv0 = __ldg(&bias[c0]);
        float bv1 = __ldg(&bias[c1]);
        float* r0 = outB + (size_t)c0 * NPIX + pbB;
        float* r1 = outB + (size_t)c1 * NPIX + pbB;
#pragma unroll
        for (int ni = 0; ni < 4; ni++) {
            int pcol = ni * 8 + 2 * t;
            float2 v0 = make_float2(acc[mi][ni][0] + bv0, acc[mi][ni][1] + bv0);
            float2 v1 = make_float2(acc[mi][ni][2] + bv1, acc[mi][ni][3] + bv1);
            *reinterpret_cast<float2*>(r0 + pcol) = v0;
            *reinterpret_cast<float2*>(r1 + pcol) = v1;
        }
    }
}

// ===========================================================================
extern "C" void kernel_launch(void* const* d_in, const int* in_sizes, int n_in,
                              void* d_out, int out_size)
{
    const float* x        = (const float*)d_in[0];
    const float* weight   = (const float*)d_in[1];
    const float* bias     = (const float*)d_in[2];
    const float* offset_w = (const float*)d_in[3];
    const float* offset_b = (const float*)d_in[4];
    float* out = (float*)d_out;

    cudaFuncSetAttribute(gemm_kernel,
                         cudaFuncAttributeMaxDynamicSharedMemorySize, GEMM_SMEM);

    // 0) weight hi/lo split
    wsplit_kernel<<<(COUT * KDIM + 255) / 256, 256>>>(weight);

    // 1) offset conv partials (4 channel slices)
    dim3 ogrid(MTOT / 256, 4);
    offset_partial_kernel<<<ogrid, 256>>>(x, offset_w);

    // 2) finalize offsets
    offset_final_kernel<<<MTOT / 256, 256>>>(offset_b);

    // 3) bilinear gather -> bf16 hi/lo A matrix
    dim3 ggrid(MTOT / 256, KKN);
    gather_kernel<<<ggrid, 256>>>(x);

    // 4) HMMA GEMM + bias (cp.async pipelined)
    dim3 mgrid(MTOT / 128, COUT / 128);
    gemm_kernel<<<mgrid, 256, GEMM_SMEM>>>(bias, out);
}

// round 8
// speedup vs baseline: 2.4417x; 1.0942x over previous
#include <cuda_runtime.h>
#include <cuda_bf16.h>
#include <cstdint>

// ---------------------------------------------------------------------------
// DCNv2: B=8, Cin=Cout=256, H=W=64, K=3, S=1, P=1, D=1
// Pipeline:
//   0) wsplit:         weight -> Whi/Wlo (bf16 split), [cout][k]
//   1) offset_partial: 8 channel-slices (32 ch) of 3x3 offset conv -> g_om8
//   2) offset_final:   sum + bias, sigmoid mask, sampling positions
//   3) gather:         bilinear sample * mask -> A bf16 hi/lo, K-major [k][m]
//                      (c-split x2 for occupancy)
//   4) gemm:           mma.sync m16n8k16 bf16, 3-term compensated split,
//                      cp.async 6-stage pipeline, term-major mma order
//                      (at legacy HMMA ceiling ~512 MAC/cyc/SM)
// (tcgen05 unavailable: harness PTX target is compute_103, no 'a' features)
// ---------------------------------------------------------------------------

#define BDIM   8
#define CIN    256
#define COUT   256
#define KKN    9
#define NPIX   4096
#define MTOT   32768
#define KDIM   2304

// ------------------------- scratch (device globals) ------------------------
__device__ float g_py[BDIM * KKN * NPIX];
__device__ float g_px[BDIM * KKN * NPIX];
__device__ float g_pm[BDIM * KKN * NPIX];
__device__ float g_om8[8 * 27 * MTOT];                 // 28.3 MB partials
__device__ __nv_bfloat16 g_Ahi[(size_t)KDIM * MTOT];   // [k][m]
__device__ __nv_bfloat16 g_Alo[(size_t)KDIM * MTOT];
__device__ __nv_bfloat16 g_Whi[COUT * KDIM];           // [n][k]
__device__ __nv_bfloat16 g_Wlo[COUT * KDIM];

// ------------------------- PTX wrappers ------------------------------------
static __device__ __forceinline__ uint32_t smem_u32(const void* p) {
    return (uint32_t)__cvta_generic_to_shared(p);
}
static __device__ __forceinline__ void ldsm_x4(uint32_t& r0, uint32_t& r1,
                                               uint32_t& r2, uint32_t& r3,
                                               uint32_t addr) {
    asm volatile("ldmatrix.sync.aligned.m8n8.x4.shared.b16 {%0,%1,%2,%3}, [%4];"
                 : "=r"(r0), "=r"(r1), "=r"(r2), "=r"(r3) : "r"(addr));
}
static __device__ __forceinline__ void ldsm_x4_t(uint32_t& r0, uint32_t& r1,
                                                 uint32_t& r2, uint32_t& r3,
                                                 uint32_t addr) {
    asm volatile("ldmatrix.sync.aligned.m8n8.x4.trans.shared.b16 {%0,%1,%2,%3}, [%4];"
                 : "=r"(r0), "=r"(r1), "=r"(r2), "=r"(r3) : "r"(addr));
}
static __device__ __forceinline__ void mma_bf16(float* d, const uint32_t* a,
                                                uint32_t b0, uint32_t b1) {
    asm volatile(
        "mma.sync.aligned.m16n8k16.row.col.f32.bf16.bf16.f32 "
        "{%0,%1,%2,%3},{%4,%5,%6,%7},{%8,%9},{%0,%1,%2,%3};"
        : "+f"(d[0]), "+f"(d[1]), "+f"(d[2]), "+f"(d[3])
        : "r"(a[0]), "r"(a[1]), "r"(a[2]), "r"(a[3]), "r"(b0), "r"(b1));
}
static __device__ __forceinline__ void cpasync16(uint32_t dst, const void* src) {
    asm volatile("cp.async.cg.shared.global [%0], [%1], 16;"
                 :: "r"(dst), "l"(src) : "memory");
}
static __device__ __forceinline__ void cp_commit() {
    asm volatile("cp.async.commit_group;" ::: "memory");
}
static __device__ __forceinline__ void cp_wait4() {
    asm volatile("cp.async.wait_group 4;" ::: "memory");
}

// ===========================================================================
// Kernel 0: weight bf16 hi/lo split
// ===========================================================================
__global__ __launch_bounds__(256) void wsplit_kernel(const float* __restrict__ w)
{
    int i = blockIdx.x * 256 + threadIdx.x;
    if (i < COUT * KDIM) {
        float v = w[i];
        __nv_bfloat16 h = __float2bfloat16(v);
        float hf = __bfloat162float(h);
        g_Whi[i] = h;
        g_Wlo[i] = __float2bfloat16(v - hf);
    }
}

// ===========================================================================
// Kernel 1: offset conv partial (one 32-channel slice per blockIdx.y, 8 total)
// ===========================================================================
__global__ __launch_bounds__(256) void offset_partial_kernel(
    const float* __restrict__ x,
    const float* __restrict__ ow)
{
    const int tid = threadIdx.x;
    const int m   = blockIdx.x * 256 + tid;
    const int sl  = blockIdx.y;                 // slice 0..7
    const int b   = m >> 12;
    const int p   = m & 4095;
    const int ho  = p >> 6;
    const int wo  = p & 63;

    __shared__ __align__(16) float ws[32 * 9 * 28];

    float acc[28];
#pragma unroll
    for (int i = 0; i < 28; i++) acc[i] = 0.f;

    const bool r0ok = (ho > 0), r2ok = (ho < 63);
    const bool c0ok = (wo > 0), c2ok = (wo < 63);

    const int c0 = sl * 32;
    // stage weights: coalesced gmem walk, scatter to smem
    for (int idx = tid; idx < 27 * 32 * 9; idx += 256) {
        int oc  = idx / 288;
        int rem = idx % 288;
        int c   = rem / 9;
        int kk  = rem % 9;
        ws[c * 252 + kk * 28 + oc] = ow[(oc * CIN + c0 + c) * 9 + kk];
    }
    for (int idx = tid; idx < 288; idx += 256) {
        int c = idx / 9, kk = idx % 9;
        ws[c * 252 + kk * 28 + 27] = 0.f;
    }
    __syncthreads();

#pragma unroll 1
    for (int c = 0; c < 32; ++c) {
        const float* xc = x + ((size_t)(b * CIN + c0 + c)) * NPIX;
        float xv[9];
#pragma unroll
        for (int ki = 0; ki < 3; ki++) {
#pragma unroll
            for (int kj = 0; kj < 3; kj++) {
                bool rok = (ki == 0) ? r0ok : ((ki == 2) ? r2ok : true);
                bool cok = (kj == 0) ? c0ok : ((kj == 2) ? c2ok : true);
                int yy = ho - 1 + ki, xx = wo - 1 + kj;
                xv[ki * 3 + kj] = (rok && cok) ? xc[yy * 64 + xx] : 0.f;
            }
        }
#pragma unroll
        for (int kk = 0; kk < 9; kk++) {
            float xvk = xv[kk];
            const float4* wrow =
                reinterpret_cast<const float4*>(&ws[c * 252 + kk * 28]);
#pragma unroll
            for (int o4 = 0; o4 < 7; o4++) {
                float4 w = wrow[o4];
                acc[o4 * 4 + 0] += xvk * w.x;
                acc[o4 * 4 + 1] += xvk * w.y;
                acc[o4 * 4 + 2] += xvk * w.z;
                acc[o4 * 4 + 3] += xvk * w.w;
            }
        }
    }

#pragma unroll
    for (int i = 0; i < 27; i++)
        g_om8[((size_t)(sl * 27 + i)) * MTOT + m] = acc[i];
}

// ===========================================================================
// Kernel 2: offset finalize -> py / px / mask  (sums 8 slices)
// ===========================================================================
__global__ __launch_bounds__(256) void offset_final_kernel(
    const float* __restrict__ ob)
{
    const int m  = blockIdx.x * 256 + threadIdx.x;
    const int b  = m >> 12;
    const int p  = m & 4095;
    const int ho = p >> 6;
    const int wo = p & 63;

    float acc[27];
#pragma unroll
    for (int i = 0; i < 27; i++) {
        float s = 0.f;
#pragma unroll
        for (int sl = 0; sl < 8; sl++)
            s += g_om8[((size_t)(sl * 27 + i)) * MTOT + m];
        acc[i] = s;
    }

#pragma unroll
    for (int kk = 0; kk < 9; kk++) {
        float dy = acc[2 * kk]     + ob[2 * kk];
        float dx = acc[2 * kk + 1] + ob[2 * kk + 1];
        float mv = acc[18 + kk]    + ob[18 + kk];
        mv = 1.f / (1.f + __expf(-mv));
        int ki = kk / 3, kj = kk % 3;
        float pyv = dy + (float)(ho - 1 + ki);
        float pxv = dx + (float)(wo - 1 + kj);
        int o = ((b * 9 + kk) << 12) + p;
        g_py[o] = pyv;
        g_px[o] = pxv;
        g_pm[o] = mv;
    }
}

// ===========================================================================
// Kernel 3: bilinear gather -> A bf16 hi/lo, K-major g_A*[k = c*9+kk][m]
//   c-split: blockIdx.z in {0,1}, 128 channels each (2x occupancy)
// ===========================================================================
__global__ __launch_bounds__(256) void gather_kernel(const float* __restrict__ x)
{
    const int tid = threadIdx.x;
    const int m   = blockIdx.x * 256 + tid;
    const int kk  = blockIdx.y;
    const int cs  = blockIdx.z * 128;          // channel slice base
    const int b   = m >> 12;
    const int p   = m & 4095;

    const int o = ((b * 9 + kk) << 12) + p;
    const float pyv = g_py[o];
    const float pxv = g_px[o];
    const float mv  = g_pm[o];

    float y0f = floorf(pyv), x0f = floorf(pxv);
    float wy1 = pyv - y0f, wx1 = pxv - x0f;
    float wy0 = 1.f - wy1, wx0 = 1.f - wx1;
    int y0 = (int)y0f, x0 = (int)x0f;
    int y1 = y0 + 1,   x1 = x0 + 1;

    float w00 = wy0 * wx0 * mv, w01 = wy0 * wx1 * mv;
    float w10 = wy1 * wx0 * mv, w11 = wy1 * wx1 * mv;
    if (y0 < 0 || y0 > 63) { w00 = 0.f; w01 = 0.f; }
    if (y1 < 0 || y1 > 63) { w10 = 0.f; w11 = 0.f; }
    if (x0 < 0 || x0 > 63) { w00 = 0.f; w10 = 0.f; }
    if (x1 < 0 || x1 > 63) { w01 = 0.f; w11 = 0.f; }

    int y0c = min(max(y0, 0), 63), y1c = min(max(y1, 0), 63);
    int x0c = min(max(x0, 0), 63), x1c = min(max(x1, 0), 63);
    const int o00 = y0c * 64 + x0c, o01 = y0c * 64 + x1c;
    const int o10 = y1c * 64 + x0c, o11 = y1c * 64 + x1c;

    const float* xb = x + (size_t)(b * CIN + cs) * NPIX;
    const size_t base = (size_t)kk * MTOT + m + (size_t)cs * 9 * MTOT;

#pragma unroll 8
    for (int c = 0; c < 128; ++c) {
        const float* xc = xb + (size_t)c * NPIX;
        float v = w00 * xc[o00] + w01 * xc[o01] +
                  w10 * xc[o10] + w11 * xc[o11];
        __nv_bfloat16 h = __float2bfloat16(v);
        float hf = __bfloat162float(h);
        __nv_bfloat16 l = __float2bfloat16(v - hf);
        size_t idx = base + (size_t)c * 9 * MTOT;   // k = (cs+c)*9 + kk
        g_Ahi[idx] = h;
        g_Alo[idx] = l;
    }
}

// ===========================================================================
// Kernel 4: HMMA GEMM  out[cout][m] = sum_k W[cout][k] * A[k][m]
//   Block tile 128 cout x 128 pixels, 8 warps (warp tile 64x32).
//   6-stage cp.async ring (BK=16, 18 KB/stage), one barrier per stage.
//   48 mma per warp per stage, term-major (16 independent accs per sweep).
// ===========================================================================
#define NSTG      6
#define STG_BYTES 18432
#define OFF_BHI   10240
#define OFF_BLO   14336
#define GEMM_SMEM (NSTG * STG_BYTES)   // 110592

__global__ __launch_bounds__(256, 1) void gemm_kernel(
    const float* __restrict__ bias,
    float* __restrict__ out)
{
    extern __shared__ __align__(1024) unsigned char smem[];
    const uint32_t sbase = smem_u32(smem);
    const int tid  = threadIdx.x;
    const int warp = tid >> 5;
    const int lane = tid & 31;
    const int mBase    = blockIdx.x * 128;   // pixel base
    const int coutBase = blockIdx.y * 128;

    // ------ staging indices ------
    const int am = tid >> 1;          // A: cout row in tile 0..127
    const int ah = tid & 1;           // A: 0=hi, 1=lo
    const int bk = tid >> 4;          // B: k row 0..15
    const int bc = tid & 15;          // B: pixel chunk (8 bf16)

    const char* gA  = reinterpret_cast<const char*>(
        (ah ? g_Wlo : g_Whi) + (size_t)(coutBase + am) * KDIM);
    const char* gBh = reinterpret_cast<const char*>(
        g_Ahi + (size_t)bk * MTOT + mBase + bc * 8);
    const char* gBl = reinterpret_cast<const char*>(
        g_Alo + (size_t)bk * MTOT + mBase + bc * 8);

    const uint32_t aSts = (uint32_t)(am * 80 + ah * 32);
    const uint32_t bSts = (uint32_t)(bk * 256 + ((bc ^ (bk & 7)) * 16));

    // ------ fragment addresses ------
    const int wm = (warp >> 2) * 64;
    const int wn = (warp & 3) * 32;
    const uint32_t aAddrBase = sbase +
        (uint32_t)((wm + (lane & 15)) * 80 + ((lane >> 4) & 1) * 16);
    const int kRow   = (lane & 7) + ((lane >> 3) & 1) * 8;
    const int chBase = (wn >> 3) + ((lane >> 4) & 1);
    const uint32_t bOff = (uint32_t)(kRow * 256);
    const uint32_t ch0 = (uint32_t)(((chBase + 0) ^ (kRow & 7)) * 16);
    const uint32_t ch1 = (uint32_t)(((chBase + 2) ^ (kRow & 7)) * 16);

    float acc[4][4][4];
#pragma unroll
    for (int i = 0; i < 4; i++)
#pragma unroll
        for (int j = 0; j < 4; j++)
#pragma unroll
            for (int r = 0; r < 4; r++) acc[i][j][r] = 0.f;

    const int NK = KDIM / 16;   // 144

    auto issue = [&](int kt, int buf) {
        const uint32_t sb = sbase + (uint32_t)(buf * STG_BYTES);
        const char* sa  = gA  + (size_t)kt * 32;
        const char* sbh = gBh + (size_t)kt * 16 * MTOT * 2;
        const char* sbl = gBl + (size_t)kt * 16 * MTOT * 2;
        cpasync16(sb + aSts,          sa);
        cpasync16(sb + aSts + 16,     sa + 16);
        cpasync16(sb + OFF_BHI + bSts, sbh);
        cpasync16(sb + OFF_BLO + bSts, sbl);
        cp_commit();
    };

#pragma unroll
    for (int kt = 0; kt < 5; ++kt) issue(kt, kt);

    for (int kt = 0; kt < NK; ++kt) {
        const int buf = kt % NSTG;
        cp_wait4();
        __syncthreads();

        const uint32_t stg = (uint32_t)(buf * STG_BYTES);

        uint32_t ahi[4][4], alo[4][4];
#pragma unroll
        for (int mi = 0; mi < 4; mi++) {
            uint32_t ad = aAddrBase + stg + (uint32_t)(mi * 16 * 80);
            ldsm_x4(ahi[mi][0], ahi[mi][1], ahi[mi][2], ahi[mi][3], ad);
            ldsm_x4(alo[mi][0], alo[mi][1], alo[mi][2], alo[mi][3], ad + 32);
        }
        uint32_t bhi[2][4], blo[2][4];
        {
            const uint32_t hbase = sbase + OFF_BHI + stg + bOff;
            const uint32_t lbase = sbase + OFF_BLO + stg + bOff;
            ldsm_x4_t(bhi[0][0], bhi[0][1], bhi[0][2], bhi[0][3], hbase + ch0);
            ldsm_x4_t(bhi[1][0], bhi[1][1], bhi[1][2], bhi[1][3], hbase + ch1);
            ldsm_x4_t(blo[0][0], blo[0][1], blo[0][2], blo[0][3], lbase + ch0);
            ldsm_x4_t(blo[1][0], blo[1][1], blo[1][2], blo[1][3], lbase + ch1);
        }

        if (kt + 5 < NK) issue(kt + 5, (kt + 5) % NSTG);
        else             cp_commit();

#pragma unroll
        for (int mi = 0; mi < 4; mi++)
#pragma unroll
            for (int nj = 0; nj < 2; nj++)
#pragma unroll
                for (int h = 0; h < 2; h++)
                    mma_bf16(acc[mi][nj * 2 + h], ahi[mi],
                             bhi[nj][2 * h], bhi[nj][2 * h + 1]);
#pragma unroll
        for (int mi = 0; mi < 4; mi++)
#pragma unroll
            for (int nj = 0; nj < 2; nj++)
#pragma unroll
                for (int h = 0; h < 2; h++)
                    mma_bf16(acc[mi][nj * 2 + h], ahi[mi],
                             blo[nj][2 * h], blo[nj][2 * h + 1]);
#pragma unroll
        for (int mi = 0; mi < 4; mi++)
#pragma unroll
            for (int nj = 0; nj < 2; nj++)
#pragma unroll
                for (int h = 0; h < 2; h++)
                    mma_bf16(acc[mi][nj * 2 + h], alo[mi],
                             bhi[nj][2 * h], bhi[nj][2 * h + 1]);

        __syncthreads();
    }

    // ---- epilogue ----
    const int g = lane >> 2;
    const int t = lane & 3;
    const int b    = mBase >> 12;
    const int pbB  = (mBase & 4095) + wn;
    float* outB = out + (size_t)b * COUT * NPIX;

#pragma unroll
    for (int mi = 0; mi < 4; mi++) {
        int c0 = coutBase + wm + mi * 16 + g;
        int c1 = c0 + 8;
        float bv0 = __ldg(&bias[c0]);
        float bv1 = __ldg(&bias[c1]);
        float* r0 = outB + (size_t)c0 * NPIX + pbB;
        float* r1 = outB + (size_t)c1 * NPIX + pbB;
#pragma unroll
        for (int ni = 0; ni < 4; ni++) {
            int pcol = ni * 8 + 2 * t;
            float2 v0 = make_float2(acc[mi][ni][0] + bv0, acc[mi][ni][1] + bv0);
            float2 v1 = make_float2(acc[mi][ni][2] + bv1, acc[mi][ni][3] + bv1);
            *reinterpret_cast<float2*>(r0 + pcol) = v0;
            *reinterpret_cast<float2*>(r1 + pcol) = v1;
        }
    }
}

// ===========================================================================
extern "C" void kernel_launch(void* const* d_in, const int* in_sizes, int n_in,
                              void* d_out, int out_size)
{
    const float* x        = (const float*)d_in[0];
    const float* weight   = (const float*)d_in[1];
    const float* bias     = (const float*)d_in[2];
    const float* offset_w = (const float*)d_in[3];
    const float* offset_b = (const float*)d_in[4];
    float* out = (float*)d_out;

    cudaFuncSetAttribute(gemm_kernel,
                         cudaFuncAttributeMaxDynamicSharedMemorySize, GEMM_SMEM);

    // 0) weight hi/lo split
    wsplit_kernel<<<(COUT * KDIM + 255) / 256, 256>>>(weight);

    // 1) offset conv partials (8 channel slices of 32)
    dim3 ogrid(MTOT / 256, 8);
    offset_partial_kernel<<<ogrid, 256>>>(x, offset_w);

    // 2) finalize offsets
    offset_final_kernel<<<MTOT / 256, 256>>>(offset_b);

    // 3) bilinear gather -> bf16 hi/lo A matrix (c-split x2)
    dim3 ggrid(MTOT / 256, KKN, 2);
    gather_kernel<<<ggrid, 256>>>(x);

    // 4) HMMA GEMM + bias (cp.async pipelined)
    dim3 mgrid(MTOT / 128, COUT / 128);
    gemm_kernel<<<mgrid, 256, GEMM_SMEM>>>(bias, out);
}